// round 3
// baseline (speedup 1.0000x reference)
#include <cuda_runtime.h>
#include <math.h>
#include <stdint.h>

// ---------------------------------------------------------------------------
// ShiftWindowAttentionBlock  (B=32, M=8, P=256, D=512, H=4, A=64, WS=4, SH=2)
//
//   1) Q,K,V = roll(x,-2) @ W{q,k,v}^T + b    (fused tf32-split MMA GEMM)
//   2) window attention (WS=4, mask only on window 63: groups [1,1,2,2])
//   3) zp  = attn @ aW^T + ab                 (tf32-split MMA GEMM)
//   4) z1  = relu(x + roll(LN(zp), +2))       (fused row epilogue)
//   5) y   = z1 @ fW^T + fb                   (tf32-split MMA GEMM)
//   6) out = relu(z1 + LN(y))                 (fused row epilogue)
//   7) merged == out viewed as [32768, 1024]  (free reinterpret)
//   8) y2  = merged @ dW^T + db               (tf32-split MMA GEMM)
//   9) d_out = relu(LN(y2))                   (fused row epilogue)
//
// GEMM: C[M,N] = A[M,K] @ W[N,K]^T + bias.  All GEMMs use tensor cores:
// fp32 operands split into hi/lo tf32 (D += Ah*Bh + Ah*Bl + Al*Bh), giving
// ~1e-6 relative error at ~3x tensor work — far faster than the FFMA pipe.
// ---------------------------------------------------------------------------

#define NTOK   65536          // B*M*P tokens

// scratch (device globals: allocation-free per harness rules)
__device__ float g_q   [NTOK * 256];
__device__ float g_k   [NTOK * 256];
__device__ float g_v   [NTOK * 256];
__device__ float g_attn[NTOK * 256];
__device__ float g_tmp [NTOK * 512];
__device__ float g_z1  [NTOK * 512];
__device__ float g_out [NTOK * 512];

// ---------------------------------------------------------------------------
// tf32 helpers
// ---------------------------------------------------------------------------
__device__ __forceinline__ uint32_t f2tf32(float x)
{
    uint32_t r;
    asm("cvt.rna.tf32.f32 %0, %1;" : "=r"(r) : "f"(x));
    return r;
}

__device__ __forceinline__ void mma_tf32(float c[4], const uint32_t a[4],
                                         const uint32_t b[2])
{
    asm volatile(
        "mma.sync.aligned.m16n8k8.row.col.f32.tf32.tf32.f32 "
        "{%0,%1,%2,%3}, {%4,%5,%6,%7}, {%8,%9}, {%0,%1,%2,%3};"
        : "+f"(c[0]), "+f"(c[1]), "+f"(c[2]), "+f"(c[3])
        : "r"(a[0]), "r"(a[1]), "r"(a[2]), "r"(a[3]), "r"(b[0]), "r"(b[1]));
}

// ---------------------------------------------------------------------------
// GEMM tile body: BM=128, BN=64, BK=16, 256 threads = 8 warps (4m x 2n),
// warp tile 32x32 = 2 m-tiles(16) x 4 n-tiles(8).
// A operand fp32 [M,K]; W fp32 [N,K]; bias[N].  roll: token-row gather
// p -> (p+2) mod 256 in the low 8 bits.
// ---------------------------------------------------------------------------
__device__ __forceinline__
void gemm_tile_tf32(const float* __restrict__ A, const float* __restrict__ W,
                    const float* __restrict__ bias, float* __restrict__ C,
                    int N, int K, int row0, int col0, bool roll)
{
    __shared__ uint32_t As_hi[16][128];
    __shared__ uint32_t As_lo[16][128];
    __shared__ uint32_t Bs_hi[16][64];
    __shared__ uint32_t Bs_lo[16][64];

    const int tid  = threadIdx.x;
    const int lane = tid & 31;
    const int warp = tid >> 5;
    const int g    = lane >> 2;         // 0..7
    const int c    = lane & 3;          // 0..3
    const int wm   = (warp >> 1) * 32;  // warp m-origin in tile
    const int wn   = (warp & 1) * 32;   // warp n-origin in tile

    float acc[2][4][4];
#pragma unroll
    for (int mi = 0; mi < 2; mi++)
#pragma unroll
        for (int nj = 0; nj < 4; nj++)
#pragma unroll
            for (int e = 0; e < 4; e++) acc[mi][nj][e] = 0.f;

    for (int k0 = 0; k0 < K; k0 += 16) {
        // ---- stage A: 128 rows x 16 k  (2 float4 per thread) ----
#pragma unroll
        for (int it = 0; it < 2; it++) {
            const int lin = tid + it * 256;
            const int r   = lin >> 2;       // 0..127 (m row)
            const int c4  = lin & 3;        // float4 index along k

            int ar = row0 + r;
            if (roll) ar = (ar & ~255) | ((ar + 2) & 255);
            const float4 va = *(const float4*)(A + (size_t)ar * K + k0 + c4 * 4);
            const float vv[4] = { va.x, va.y, va.z, va.w };
#pragma unroll
            for (int j = 0; j < 4; j++) {
                const uint32_t h = f2tf32(vv[j]);
                As_hi[c4 * 4 + j][r] = h;
                As_lo[c4 * 4 + j][r] = f2tf32(vv[j] - __uint_as_float(h));
            }
        }
        // ---- stage B: 64 rows(n) x 16 k (1 float4 per thread) ----
        {
            const int r  = tid >> 2;        // 0..63 (n row)
            const int c4 = tid & 3;
            const float4 vb = *(const float4*)(W + (size_t)(col0 + r) * K + k0 + c4 * 4);
            const float vv[4] = { vb.x, vb.y, vb.z, vb.w };
#pragma unroll
            for (int j = 0; j < 4; j++) {
                const uint32_t h = f2tf32(vv[j]);
                Bs_hi[c4 * 4 + j][r] = h;
                Bs_lo[c4 * 4 + j][r] = f2tf32(vv[j] - __uint_as_float(h));
            }
        }
        __syncthreads();

#pragma unroll
        for (int ks = 0; ks < 16; ks += 8) {
            // A fragments (m16 x k8), rows = m, cols = k
            uint32_t ah[2][4], al[2][4];
#pragma unroll
            for (int mi = 0; mi < 2; mi++) {
                const int m0 = wm + mi * 16;
                ah[mi][0] = As_hi[ks + c    ][m0 + g];
                ah[mi][1] = As_hi[ks + c    ][m0 + g + 8];
                ah[mi][2] = As_hi[ks + c + 4][m0 + g];
                ah[mi][3] = As_hi[ks + c + 4][m0 + g + 8];
                al[mi][0] = As_lo[ks + c    ][m0 + g];
                al[mi][1] = As_lo[ks + c    ][m0 + g + 8];
                al[mi][2] = As_lo[ks + c + 4][m0 + g];
                al[mi][3] = As_lo[ks + c + 4][m0 + g + 8];
            }
            // B fragments (k8 x n8)
            uint32_t bh[4][2], bl[4][2];
#pragma unroll
            for (int nj = 0; nj < 4; nj++) {
                const int n0 = wn + nj * 8;
                bh[nj][0] = Bs_hi[ks + c    ][n0 + g];
                bh[nj][1] = Bs_hi[ks + c + 4][n0 + g];
                bl[nj][0] = Bs_lo[ks + c    ][n0 + g];
                bl[nj][1] = Bs_lo[ks + c + 4][n0 + g];
            }
#pragma unroll
            for (int mi = 0; mi < 2; mi++)
#pragma unroll
                for (int nj = 0; nj < 4; nj++) {
                    mma_tf32(acc[mi][nj], ah[mi], bh[nj]);
                    mma_tf32(acc[mi][nj], ah[mi], bl[nj]);
                    mma_tf32(acc[mi][nj], al[mi], bh[nj]);
                }
        }
        __syncthreads();
    }

    // ---- epilogue: add bias, store (float2 per C-frag row pair) ----
#pragma unroll
    for (int mi = 0; mi < 2; mi++)
#pragma unroll
        for (int nj = 0; nj < 4; nj++) {
            const int gc = col0 + wn + nj * 8 + 2 * c;
            const float bx = bias[gc], by = bias[gc + 1];
            {
                const size_t gr = (size_t)(row0 + wm + mi * 16 + g);
                float2 o; o.x = acc[mi][nj][0] + bx; o.y = acc[mi][nj][1] + by;
                *(float2*)(C + gr * N + gc) = o;
            }
            {
                const size_t gr = (size_t)(row0 + wm + mi * 16 + g + 8);
                float2 o; o.x = acc[mi][nj][2] + bx; o.y = acc[mi][nj][3] + by;
                *(float2*)(C + gr * N + gc) = o;
            }
        }
}

// generic GEMM (no roll)
__global__ __launch_bounds__(256)
void sgemm_bias(const float* __restrict__ A, const float* __restrict__ W,
                const float* __restrict__ bias, float* __restrict__ C,
                int N, int K)
{
    gemm_tile_tf32(A, W, bias, C, N, K, blockIdx.y * 128, blockIdx.x * 64, false);
}

// fused QKV GEMM with rolled A-gather: blockIdx.x = sel*4 + n-tile
__global__ __launch_bounds__(256)
void qkv_gemm(const float* __restrict__ x,
              const float* __restrict__ Wq, const float* __restrict__ Wk,
              const float* __restrict__ Wv,
              const float* __restrict__ bq, const float* __restrict__ bk,
              const float* __restrict__ bv,
              float* __restrict__ q, float* __restrict__ k, float* __restrict__ v)
{
    const int sel  = blockIdx.x >> 2;
    const int col0 = (blockIdx.x & 3) * 64;
    const float* W    = (sel == 0) ? Wq : (sel == 1) ? Wk : Wv;
    const float* bias = (sel == 0) ? bq : (sel == 1) ? bk : bv;
    float*       out  = (sel == 0) ? q  : (sel == 1) ? k  : v;
    gemm_tile_tf32(x, W, bias, out, 256, 512, blockIdx.y * 128, col0, true);
}

// ---------------------------------------------------------------------------
// Window attention: one block per window (4 tokens), one warp per head.
// ---------------------------------------------------------------------------
__global__ __launch_bounds__(128)
void attn_kernel()
{
    const int wg   = blockIdx.x;           // global window, token base = wg*4
    const int h    = threadIdx.x >> 5;     // head 0..3
    const int lane = threadIdx.x & 31;
    const size_t base = (size_t)(wg << 2) * 256 + h * 64 + lane;

    float qf0[4], qf1[4], kf0[4], kf1[4], vf0[4], vf1[4];
#pragma unroll
    for (int i = 0; i < 4; i++) {
        qf0[i] = g_q[base + i * 256];  qf1[i] = g_q[base + i * 256 + 32];
        kf0[i] = g_k[base + i * 256];  kf1[i] = g_k[base + i * 256 + 32];
        vf0[i] = g_v[base + i * 256];  vf1[i] = g_v[base + i * 256 + 32];
    }

    const bool masked = ((wg & 63) == 63);

    float s[4][4];
#pragma unroll
    for (int i = 0; i < 4; i++)
#pragma unroll
        for (int j = 0; j < 4; j++) {
            float p = qf0[i] * kf0[j] + qf1[i] * kf1[j];
#pragma unroll
            for (int off = 16; off; off >>= 1)
                p += __shfl_xor_sync(0xffffffffu, p, off);
            const float m = (masked && ((i < 2) != (j < 2))) ? -100.f : 0.f;
            s[i][j] = p * 0.125f + m;   // 1/sqrt(64)
        }

#pragma unroll
    for (int i = 0; i < 4; i++) {
        const float mx = fmaxf(fmaxf(s[i][0], s[i][1]), fmaxf(s[i][2], s[i][3]));
        const float e0 = expf(s[i][0] - mx);
        const float e1 = expf(s[i][1] - mx);
        const float e2 = expf(s[i][2] - mx);
        const float e3 = expf(s[i][3] - mx);
        const float inv = 1.f / (e0 + e1 + e2 + e3);
        const float o0 = (e0 * vf0[0] + e1 * vf0[1] + e2 * vf0[2] + e3 * vf0[3]) * inv;
        const float o1 = (e0 * vf1[0] + e1 * vf1[1] + e2 * vf1[2] + e3 * vf1[3]) * inv;
        g_attn[base + i * 256]      = o0;
        g_attn[base + i * 256 + 32] = o1;
    }
}

// ---------------------------------------------------------------------------
// Row epilogues: 1 block (128 threads) per row of 512, 4 elems per thread.
// ---------------------------------------------------------------------------
__device__ __forceinline__ float2 block_sum2_128(float s1, float s2)
{
#pragma unroll
    for (int off = 16; off; off >>= 1) {
        s1 += __shfl_xor_sync(0xffffffffu, s1, off);
        s2 += __shfl_xor_sync(0xffffffffu, s2, off);
    }
    __shared__ float sh[8];
    const int w = threadIdx.x >> 5;
    if ((threadIdx.x & 31) == 0) { sh[w] = s1; sh[w + 4] = s2; }
    __syncthreads();
    return make_float2(sh[0] + sh[1] + sh[2] + sh[3],
                       sh[4] + sh[5] + sh[6] + sh[7]);
}

// z1[b,m,(p+2)%256] = relu(x[b,m,(p+2)%256] + LN(zp[b,m,p]))
__global__ __launch_bounds__(128)
void ln_shift_add_relu(const float* __restrict__ zp, const float* __restrict__ x,
                       const float* __restrict__ g, const float* __restrict__ b,
                       float* __restrict__ z1)
{
    const size_t row = blockIdx.x;
    const int    c   = threadIdx.x * 4;
    const float4 v   = *(const float4*)(zp + row * 512 + c);
    float2 ss = block_sum2_128(v.x + v.y + v.z + v.w,
                               v.x * v.x + v.y * v.y + v.z * v.z + v.w * v.w);
    const float mu   = ss.x * (1.f / 512.f);
    const float var  = ss.y * (1.f / 512.f) - mu * mu;
    const float rstd = rsqrtf(var + 1e-5f);

    const size_t orow = (row & ~(size_t)255) | ((row + 2) & 255);
    const float4 gg = *(const float4*)(g + c);
    const float4 bb = *(const float4*)(b + c);
    const float4 xv = *(const float4*)(x + orow * 512 + c);
    float4 o;
    o.x = fmaxf(xv.x + (v.x - mu) * rstd * gg.x + bb.x, 0.f);
    o.y = fmaxf(xv.y + (v.y - mu) * rstd * gg.y + bb.y, 0.f);
    o.z = fmaxf(xv.z + (v.z - mu) * rstd * gg.z + bb.z, 0.f);
    o.w = fmaxf(xv.w + (v.w - mu) * rstd * gg.w + bb.w, 0.f);
    *(float4*)(z1 + orow * 512 + c) = o;
}

// out = relu(z1 + LN(y))
__global__ __launch_bounds__(128)
void ln_add_relu(const float* __restrict__ y, const float* __restrict__ z1,
                 const float* __restrict__ g, const float* __restrict__ b,
                 float* __restrict__ out)
{
    const size_t row = blockIdx.x;
    const int    c   = threadIdx.x * 4;
    const float4 v   = *(const float4*)(y + row * 512 + c);
    float2 ss = block_sum2_128(v.x + v.y + v.z + v.w,
                               v.x * v.x + v.y * v.y + v.z * v.z + v.w * v.w);
    const float mu   = ss.x * (1.f / 512.f);
    const float var  = ss.y * (1.f / 512.f) - mu * mu;
    const float rstd = rsqrtf(var + 1e-5f);

    const float4 gg = *(const float4*)(g + c);
    const float4 bb = *(const float4*)(b + c);
    const float4 zv = *(const float4*)(z1 + row * 512 + c);
    float4 o;
    o.x = fmaxf(zv.x + (v.x - mu) * rstd * gg.x + bb.x, 0.f);
    o.y = fmaxf(zv.y + (v.y - mu) * rstd * gg.y + bb.y, 0.f);
    o.z = fmaxf(zv.z + (v.z - mu) * rstd * gg.z + bb.z, 0.f);
    o.w = fmaxf(zv.w + (v.w - mu) * rstd * gg.w + bb.w, 0.f);
    *(float4*)(out + row * 512 + c) = o;
}

// d_out = relu(LN(y2))
__global__ __launch_bounds__(128)
void ln_relu(const float* __restrict__ y, const float* __restrict__ g,
             const float* __restrict__ b, float* __restrict__ out)
{
    const size_t row = blockIdx.x;
    const int    c   = threadIdx.x * 4;
    const float4 v   = *(const float4*)(y + row * 512 + c);
    float2 ss = block_sum2_128(v.x + v.y + v.z + v.w,
                               v.x * v.x + v.y * v.y + v.z * v.z + v.w * v.w);
    const float mu   = ss.x * (1.f / 512.f);
    const float var  = ss.y * (1.f / 512.f) - mu * mu;
    const float rstd = rsqrtf(var + 1e-5f);

    const float4 gg = *(const float4*)(g + c);
    const float4 bb = *(const float4*)(b + c);
    float4 o;
    o.x = fmaxf((v.x - mu) * rstd * gg.x + bb.x, 0.f);
    o.y = fmaxf((v.y - mu) * rstd * gg.y + bb.y, 0.f);
    o.z = fmaxf((v.z - mu) * rstd * gg.z + bb.z, 0.f);
    o.w = fmaxf((v.w - mu) * rstd * gg.w + bb.w, 0.f);
    *(float4*)(out + row * 512 + c) = o;
}

// ---------------------------------------------------------------------------
extern "C" void kernel_launch(void* const* d_in, const int* in_sizes, int n_in,
                              void* d_out, int out_size)
{
    const float* x     = (const float*)d_in[0];
    const float* Wq    = (const float*)d_in[1];
    const float* bq    = (const float*)d_in[2];
    const float* Wk    = (const float*)d_in[3];
    const float* bk    = (const float*)d_in[4];
    const float* Wv    = (const float*)d_in[5];
    const float* bv    = (const float*)d_in[6];
    const float* aW    = (const float*)d_in[7];
    const float* ab    = (const float*)d_in[8];
    const float* ag    = (const float*)d_in[9];
    const float* abeta = (const float*)d_in[10];
    const float* fW    = (const float*)d_in[11];
    const float* fb    = (const float*)d_in[12];
    const float* fg    = (const float*)d_in[13];
    const float* fbeta = (const float*)d_in[14];
    const float* dW    = (const float*)d_in[15];
    const float* db    = (const float*)d_in[16];
    const float* dg    = (const float*)d_in[17];
    const float* dbeta = (const float*)d_in[18];
    float* out = (float*)d_out;

    float *pq, *pk, *pv, *pat, *ptmp, *pz1, *pout;
    cudaGetSymbolAddress((void**)&pq,   g_q);
    cudaGetSymbolAddress((void**)&pk,   g_k);
    cudaGetSymbolAddress((void**)&pv,   g_v);
    cudaGetSymbolAddress((void**)&pat,  g_attn);
    cudaGetSymbolAddress((void**)&ptmp, g_tmp);
    cudaGetSymbolAddress((void**)&pz1,  g_z1);
    cudaGetSymbolAddress((void**)&pout, g_out);

    // 1) fused QKV on rolled input: [65536,512] x [512,256]^T  (x3 outputs)
    qkv_gemm<<<dim3(12, 512), 256>>>(x, Wq, Wk, Wv, bq, bk, bv, pq, pk, pv);

    // 2) window attention
    attn_kernel<<<16384, 128>>>();

    // 3) attention projection: [65536,256] x [256,512]^T
    sgemm_bias<<<dim3(8, 512), 256>>>(pat, aW, ab, ptmp, 512, 256);

    // 4) z1 = relu(x + roll(LN(zp), +2))
    ln_shift_add_relu<<<65536, 128>>>(ptmp, x, ag, abeta, pz1);

    // 5) FFN: [65536,512] x [512,512]^T
    sgemm_bias<<<dim3(8, 512), 256>>>(pz1, fW, fb, ptmp, 512, 512);

    // 6) out = relu(z1 + LN(y))
    ln_add_relu<<<65536, 128>>>(ptmp, pz1, fg, fbeta, pout);

    // 7/8) patch-merge GEMM: out viewed as [32768,1024] x [1024,512]^T
    sgemm_bias<<<dim3(8, 256), 256>>>(pout, dW, db, ptmp, 512, 1024);

    // 9) d_out = relu(LN(y2))
    ln_relu<<<32768, 128>>>(ptmp, dg, dbeta, out);
}

// round 4
// speedup vs baseline: 2.0037x; 2.0037x over previous
#include <cuda_runtime.h>
#include <math.h>
#include <stdint.h>

// ---------------------------------------------------------------------------
// ShiftWindowAttentionBlock  (B=32, M=8, P=256, D=512, H=4, A=64, WS=4, SH=2)
//
//   1) Q,K,V = roll(x,-2) @ W{q,k,v}^T + b    (fused tf32-split MMA GEMM)
//   2) window attention (WS=4, mask only on window 63: groups [1,1,2,2])
//   3) zp  = attn @ aW^T + ab                 (tf32-split MMA GEMM)
//   4) z1  = relu(x + roll(LN(zp), +2))       (fused row epilogue)
//   5) y   = z1 @ fW^T + fb                   (tf32-split MMA GEMM)
//   6) out = relu(z1 + LN(y))                 (fused row epilogue)
//   7) merged == out viewed as [32768, 1024]  (free reinterpret)
//   8) y2  = merged @ dW^T + db               (tf32-split MMA GEMM)
//   9) d_out = relu(LN(y2))                   (fused row epilogue)
//
// GEMM v2: conflict-free XOR-swizzled smem (STS and LDS fragment loads both
// bank-injective) + 2-stage double buffer with register-staged prefetch.
// fp32 split into hi/lo tf32: D += Ah*Bh + Ah*Bl + Al*Bh  (~1e-6 rel err).
// ---------------------------------------------------------------------------

#define NTOK   65536          // B*M*P tokens

// scratch (device globals: allocation-free per harness rules)
__device__ float g_q   [NTOK * 256];
__device__ float g_k   [NTOK * 256];
__device__ float g_v   [NTOK * 256];
__device__ float g_attn[NTOK * 256];
__device__ float g_tmp [NTOK * 512];
__device__ float g_z1  [NTOK * 512];
__device__ float g_out [NTOK * 512];

// ---------------------------------------------------------------------------
// tf32 helpers
// ---------------------------------------------------------------------------
__device__ __forceinline__ uint32_t f2tf32(float x)
{
    uint32_t r;
    asm("cvt.rna.tf32.f32 %0, %1;" : "=r"(r) : "f"(x));
    return r;
}

__device__ __forceinline__ void mma_tf32(float c[4], const uint32_t a[4],
                                         const uint32_t b[2])
{
    asm volatile(
        "mma.sync.aligned.m16n8k8.row.col.f32.tf32.tf32.f32 "
        "{%0,%1,%2,%3}, {%4,%5,%6,%7}, {%8,%9}, {%0,%1,%2,%3};"
        : "+f"(c[0]), "+f"(c[1]), "+f"(c[2]), "+f"(c[3])
        : "r"(a[0]), "r"(a[1]), "r"(a[2]), "r"(a[3]), "r"(b[0]), "r"(b[1]));
}

// bank-swizzle: psi(k) = (k&3) ^ (k>>2), phys col = col ^ (psi<<3)
__device__ __forceinline__ int swzA(int k, int col)
{
    return (k << 7) + (col ^ ((((k & 3) ^ (k >> 2))) << 3));
}
__device__ __forceinline__ int swzB(int k, int col)
{
    return (k << 6) + (col ^ ((((k & 3) ^ (k >> 2))) << 3));
}

// ---------------------------------------------------------------------------
// GEMM tile body: BM=128, BN=64, BK=16, 256 threads = 8 warps (4m x 2n),
// warp tile 32x32.  C[M,N] = A[M,K] @ W[N,K]^T + bias[N].
// roll: A token-row gather p -> (p+2) mod 256 in the low 8 bits.
// ---------------------------------------------------------------------------
__device__ __forceinline__
void gemm_tile_tf32(const float* __restrict__ A, const float* __restrict__ W,
                    const float* __restrict__ bias, float* __restrict__ C,
                    int N, int K, int row0, int col0, bool roll)
{
    __shared__ uint32_t As_hi[2][16 * 128];
    __shared__ uint32_t As_lo[2][16 * 128];
    __shared__ uint32_t Bs_hi[2][16 * 64];
    __shared__ uint32_t Bs_lo[2][16 * 64];

    const int tid  = threadIdx.x;
    const int lane = tid & 31;
    const int warp = tid >> 5;
    const int g    = lane >> 2;         // 0..7
    const int c    = lane & 3;          // 0..3
    const int wm   = (warp >> 1) * 32;  // warp m-origin
    const int wn   = (warp & 1) * 32;   // warp n-origin

    // ---- staging geometry (constant across k-loop) ----
    const int rA0 = tid >> 2;           // 0..63
    const int rA1 = rA0 + 64;           // 64..127
    const int c4  = tid & 3;            // float4 index along k
    int ar0 = row0 + rA0, ar1 = row0 + rA1;
    if (roll) {
        ar0 = (ar0 & ~255) | ((ar0 + 2) & 255);
        ar1 = (ar1 & ~255) | ((ar1 + 2) & 255);
    }
    const float* pA0 = A + (size_t)ar0 * K + c4 * 4;
    const float* pA1 = A + (size_t)ar1 * K + c4 * 4;
    const float* pB  = W + (size_t)(col0 + rA0) * K + c4 * 4;

    int stA0[4], stA1[4], stB[4];       // swizzled store indices per j
#pragma unroll
    for (int j = 0; j < 4; j++) {
        const int k = c4 * 4 + j;
        stA0[j] = swzA(k, rA0);
        stA1[j] = swzA(k, rA1);
        stB[j]  = swzB(k, rA0);
    }

    float acc[2][4][4];
#pragma unroll
    for (int mi = 0; mi < 2; mi++)
#pragma unroll
        for (int nj = 0; nj < 4; nj++)
#pragma unroll
            for (int e = 0; e < 4; e++) acc[mi][nj][e] = 0.f;

    // ---- prologue: load+stage tile 0 ----
    float4 a0 = *(const float4*)(pA0);
    float4 a1 = *(const float4*)(pA1);
    float4 b0 = *(const float4*)(pB);
    {
        const float av0[4] = { a0.x, a0.y, a0.z, a0.w };
        const float av1[4] = { a1.x, a1.y, a1.z, a1.w };
        const float bv [4] = { b0.x, b0.y, b0.z, b0.w };
#pragma unroll
        for (int j = 0; j < 4; j++) {
            uint32_t h;
            h = f2tf32(av0[j]); As_hi[0][stA0[j]] = h; As_lo[0][stA0[j]] = f2tf32(av0[j] - __uint_as_float(h));
            h = f2tf32(av1[j]); As_hi[0][stA1[j]] = h; As_lo[0][stA1[j]] = f2tf32(av1[j] - __uint_as_float(h));
            h = f2tf32(bv [j]); Bs_hi[0][stB [j]] = h; Bs_lo[0][stB [j]] = f2tf32(bv [j] - __uint_as_float(h));
        }
    }
    __syncthreads();

    int st = 0;
    for (int k0 = 0; k0 < K; k0 += 16) {
        const bool has_next = (k0 + 16 < K);
        if (has_next) {
            a0 = *(const float4*)(pA0 + k0 + 16);
            a1 = *(const float4*)(pA1 + k0 + 16);
            b0 = *(const float4*)(pB  + k0 + 16);
        }

        // ---- compute current stage ----
#pragma unroll
        for (int half = 0; half < 2; half++) {
            const int q0 = half * 2;        // k = c + 4*q0  (== ks + c)
            const int q1 = half * 2 + 1;    // k = c + 4*q1  (== ks + c + 4)

            uint32_t ah[2][4], al[2][4];
#pragma unroll
            for (int mi = 0; mi < 2; mi++) {
                const int m0 = wm + mi * 16;
                const int i00 = swzA(c + 4 * q0, m0 + g);
                const int i01 = swzA(c + 4 * q0, m0 + g + 8);
                const int i10 = swzA(c + 4 * q1, m0 + g);
                const int i11 = swzA(c + 4 * q1, m0 + g + 8);
                ah[mi][0] = As_hi[st][i00];  al[mi][0] = As_lo[st][i00];
                ah[mi][1] = As_hi[st][i01];  al[mi][1] = As_lo[st][i01];
                ah[mi][2] = As_hi[st][i10];  al[mi][2] = As_lo[st][i10];
                ah[mi][3] = As_hi[st][i11];  al[mi][3] = As_lo[st][i11];
            }
            uint32_t bh[4][2], bl[4][2];
#pragma unroll
            for (int nj = 0; nj < 4; nj++) {
                const int n0 = wn + nj * 8;
                const int i0 = swzB(c + 4 * q0, n0 + g);
                const int i1 = swzB(c + 4 * q1, n0 + g);
                bh[nj][0] = Bs_hi[st][i0];  bl[nj][0] = Bs_lo[st][i0];
                bh[nj][1] = Bs_hi[st][i1];  bl[nj][1] = Bs_lo[st][i1];
            }
#pragma unroll
            for (int mi = 0; mi < 2; mi++)
#pragma unroll
                for (int nj = 0; nj < 4; nj++) {
                    mma_tf32(acc[mi][nj], ah[mi], bh[nj]);
                    mma_tf32(acc[mi][nj], ah[mi], bl[nj]);
                    mma_tf32(acc[mi][nj], al[mi], bh[nj]);
                }
        }

        // ---- stage next tile into the other buffer ----
        if (has_next) {
            const int ns = st ^ 1;
            const float av0[4] = { a0.x, a0.y, a0.z, a0.w };
            const float av1[4] = { a1.x, a1.y, a1.z, a1.w };
            const float bv [4] = { b0.x, b0.y, b0.z, b0.w };
#pragma unroll
            for (int j = 0; j < 4; j++) {
                uint32_t h;
                h = f2tf32(av0[j]); As_hi[ns][stA0[j]] = h; As_lo[ns][stA0[j]] = f2tf32(av0[j] - __uint_as_float(h));
                h = f2tf32(av1[j]); As_hi[ns][stA1[j]] = h; As_lo[ns][stA1[j]] = f2tf32(av1[j] - __uint_as_float(h));
                h = f2tf32(bv [j]); Bs_hi[ns][stB [j]] = h; Bs_lo[ns][stB [j]] = f2tf32(bv [j] - __uint_as_float(h));
            }
        }
        __syncthreads();
        st ^= 1;
    }

    // ---- epilogue: add bias, store ----
#pragma unroll
    for (int mi = 0; mi < 2; mi++)
#pragma unroll
        for (int nj = 0; nj < 4; nj++) {
            const int gc = col0 + wn + nj * 8 + 2 * c;
            const float bx = bias[gc], by = bias[gc + 1];
            {
                const size_t gr = (size_t)(row0 + wm + mi * 16 + g);
                float2 o; o.x = acc[mi][nj][0] + bx; o.y = acc[mi][nj][1] + by;
                *(float2*)(C + gr * N + gc) = o;
            }
            {
                const size_t gr = (size_t)(row0 + wm + mi * 16 + g + 8);
                float2 o; o.x = acc[mi][nj][2] + bx; o.y = acc[mi][nj][3] + by;
                *(float2*)(C + gr * N + gc) = o;
            }
        }
}

// generic GEMM (no roll)
__global__ __launch_bounds__(256, 2)
void sgemm_bias(const float* __restrict__ A, const float* __restrict__ W,
                const float* __restrict__ bias, float* __restrict__ C,
                int N, int K)
{
    gemm_tile_tf32(A, W, bias, C, N, K, blockIdx.y * 128, blockIdx.x * 64, false);
}

// fused QKV GEMM with rolled A-gather: blockIdx.x = sel*4 + n-tile
__global__ __launch_bounds__(256, 2)
void qkv_gemm(const float* __restrict__ x,
              const float* __restrict__ Wq, const float* __restrict__ Wk,
              const float* __restrict__ Wv,
              const float* __restrict__ bq, const float* __restrict__ bk,
              const float* __restrict__ bv,
              float* __restrict__ q, float* __restrict__ k, float* __restrict__ v)
{
    const int sel  = blockIdx.x >> 2;
    const int col0 = (blockIdx.x & 3) * 64;
    const float* W    = (sel == 0) ? Wq : (sel == 1) ? Wk : Wv;
    const float* bias = (sel == 0) ? bq : (sel == 1) ? bk : bv;
    float*       out  = (sel == 0) ? q  : (sel == 1) ? k  : v;
    gemm_tile_tf32(x, W, bias, out, 256, 512, blockIdx.y * 128, col0, true);
}

// ---------------------------------------------------------------------------
// Window attention: one block per window (4 tokens), one warp per head.
// ---------------------------------------------------------------------------
__global__ __launch_bounds__(128)
void attn_kernel()
{
    const int wg   = blockIdx.x;           // global window, token base = wg*4
    const int h    = threadIdx.x >> 5;     // head 0..3
    const int lane = threadIdx.x & 31;
    const size_t base = (size_t)(wg << 2) * 256 + h * 64 + lane;

    float qf0[4], qf1[4], kf0[4], kf1[4], vf0[4], vf1[4];
#pragma unroll
    for (int i = 0; i < 4; i++) {
        qf0[i] = g_q[base + i * 256];  qf1[i] = g_q[base + i * 256 + 32];
        kf0[i] = g_k[base + i * 256];  kf1[i] = g_k[base + i * 256 + 32];
        vf0[i] = g_v[base + i * 256];  vf1[i] = g_v[base + i * 256 + 32];
    }

    const bool masked = ((wg & 63) == 63);

    float s[4][4];
#pragma unroll
    for (int i = 0; i < 4; i++)
#pragma unroll
        for (int j = 0; j < 4; j++) {
            float p = qf0[i] * kf0[j] + qf1[i] * kf1[j];
#pragma unroll
            for (int off = 16; off; off >>= 1)
                p += __shfl_xor_sync(0xffffffffu, p, off);
            const float m = (masked && ((i < 2) != (j < 2))) ? -100.f : 0.f;
            s[i][j] = p * 0.125f + m;   // 1/sqrt(64)
        }

#pragma unroll
    for (int i = 0; i < 4; i++) {
        const float mx = fmaxf(fmaxf(s[i][0], s[i][1]), fmaxf(s[i][2], s[i][3]));
        const float e0 = expf(s[i][0] - mx);
        const float e1 = expf(s[i][1] - mx);
        const float e2 = expf(s[i][2] - mx);
        const float e3 = expf(s[i][3] - mx);
        const float inv = 1.f / (e0 + e1 + e2 + e3);
        const float o0 = (e0 * vf0[0] + e1 * vf0[1] + e2 * vf0[2] + e3 * vf0[3]) * inv;
        const float o1 = (e0 * vf1[0] + e1 * vf1[1] + e2 * vf1[2] + e3 * vf1[3]) * inv;
        g_attn[base + i * 256]      = o0;
        g_attn[base + i * 256 + 32] = o1;
    }
}

// ---------------------------------------------------------------------------
// Row epilogues: 1 block (128 threads) per row of 512, 4 elems per thread.
// ---------------------------------------------------------------------------
__device__ __forceinline__ float2 block_sum2_128(float s1, float s2)
{
#pragma unroll
    for (int off = 16; off; off >>= 1) {
        s1 += __shfl_xor_sync(0xffffffffu, s1, off);
        s2 += __shfl_xor_sync(0xffffffffu, s2, off);
    }
    __shared__ float sh[8];
    const int w = threadIdx.x >> 5;
    if ((threadIdx.x & 31) == 0) { sh[w] = s1; sh[w + 4] = s2; }
    __syncthreads();
    return make_float2(sh[0] + sh[1] + sh[2] + sh[3],
                       sh[4] + sh[5] + sh[6] + sh[7]);
}

// z1[b,m,(p+2)%256] = relu(x[b,m,(p+2)%256] + LN(zp[b,m,p]))
__global__ __launch_bounds__(128)
void ln_shift_add_relu(const float* __restrict__ zp, const float* __restrict__ x,
                       const float* __restrict__ g, const float* __restrict__ b,
                       float* __restrict__ z1)
{
    const size_t row = blockIdx.x;
    const int    c   = threadIdx.x * 4;
    const float4 v   = *(const float4*)(zp + row * 512 + c);
    float2 ss = block_sum2_128(v.x + v.y + v.z + v.w,
                               v.x * v.x + v.y * v.y + v.z * v.z + v.w * v.w);
    const float mu   = ss.x * (1.f / 512.f);
    const float var  = ss.y * (1.f / 512.f) - mu * mu;
    const float rstd = rsqrtf(var + 1e-5f);

    const size_t orow = (row & ~(size_t)255) | ((row + 2) & 255);
    const float4 gg = *(const float4*)(g + c);
    const float4 bb = *(const float4*)(b + c);
    const float4 xv = *(const float4*)(x + orow * 512 + c);
    float4 o;
    o.x = fmaxf(xv.x + (v.x - mu) * rstd * gg.x + bb.x, 0.f);
    o.y = fmaxf(xv.y + (v.y - mu) * rstd * gg.y + bb.y, 0.f);
    o.z = fmaxf(xv.z + (v.z - mu) * rstd * gg.z + bb.z, 0.f);
    o.w = fmaxf(xv.w + (v.w - mu) * rstd * gg.w + bb.w, 0.f);
    *(float4*)(z1 + orow * 512 + c) = o;
}

// out = relu(z1 + LN(y))
__global__ __launch_bounds__(128)
void ln_add_relu(const float* __restrict__ y, const float* __restrict__ z1,
                 const float* __restrict__ g, const float* __restrict__ b,
                 float* __restrict__ out)
{
    const size_t row = blockIdx.x;
    const int    c   = threadIdx.x * 4;
    const float4 v   = *(const float4*)(y + row * 512 + c);
    float2 ss = block_sum2_128(v.x + v.y + v.z + v.w,
                               v.x * v.x + v.y * v.y + v.z * v.z + v.w * v.w);
    const float mu   = ss.x * (1.f / 512.f);
    const float var  = ss.y * (1.f / 512.f) - mu * mu;
    const float rstd = rsqrtf(var + 1e-5f);

    const float4 gg = *(const float4*)(g + c);
    const float4 bb = *(const float4*)(b + c);
    const float4 zv = *(const float4*)(z1 + row * 512 + c);
    float4 o;
    o.x = fmaxf(zv.x + (v.x - mu) * rstd * gg.x + bb.x, 0.f);
    o.y = fmaxf(zv.y + (v.y - mu) * rstd * gg.y + bb.y, 0.f);
    o.z = fmaxf(zv.z + (v.z - mu) * rstd * gg.z + bb.z, 0.f);
    o.w = fmaxf(zv.w + (v.w - mu) * rstd * gg.w + bb.w, 0.f);
    *(float4*)(out + row * 512 + c) = o;
}

// d_out = relu(LN(y2))
__global__ __launch_bounds__(128)
void ln_relu(const float* __restrict__ y, const float* __restrict__ g,
             const float* __restrict__ b, float* __restrict__ out)
{
    const size_t row = blockIdx.x;
    const int    c   = threadIdx.x * 4;
    const float4 v   = *(const float4*)(y + row * 512 + c);
    float2 ss = block_sum2_128(v.x + v.y + v.z + v.w,
                               v.x * v.x + v.y * v.y + v.z * v.z + v.w * v.w);
    const float mu   = ss.x * (1.f / 512.f);
    const float var  = ss.y * (1.f / 512.f) - mu * mu;
    const float rstd = rsqrtf(var + 1e-5f);

    const float4 gg = *(const float4*)(g + c);
    const float4 bb = *(const float4*)(b + c);
    float4 o;
    o.x = fmaxf((v.x - mu) * rstd * gg.x + bb.x, 0.f);
    o.y = fmaxf((v.y - mu) * rstd * gg.y + bb.y, 0.f);
    o.z = fmaxf((v.z - mu) * rstd * gg.z + bb.z, 0.f);
    o.w = fmaxf((v.w - mu) * rstd * gg.w + bb.w, 0.f);
    *(float4*)(out + row * 512 + c) = o;
}

// ---------------------------------------------------------------------------
extern "C" void kernel_launch(void* const* d_in, const int* in_sizes, int n_in,
                              void* d_out, int out_size)
{
    const float* x     = (const float*)d_in[0];
    const float* Wq    = (const float*)d_in[1];
    const float* bq    = (const float*)d_in[2];
    const float* Wk    = (const float*)d_in[3];
    const float* bk    = (const float*)d_in[4];
    const float* Wv    = (const float*)d_in[5];
    const float* bv    = (const float*)d_in[6];
    const float* aW    = (const float*)d_in[7];
    const float* ab    = (const float*)d_in[8];
    const float* ag    = (const float*)d_in[9];
    const float* abeta = (const float*)d_in[10];
    const float* fW    = (const float*)d_in[11];
    const float* fb    = (const float*)d_in[12];
    const float* fg    = (const float*)d_in[13];
    const float* fbeta = (const float*)d_in[14];
    const float* dW    = (const float*)d_in[15];
    const float* db    = (const float*)d_in[16];
    const float* dg    = (const float*)d_in[17];
    const float* dbeta = (const float*)d_in[18];
    float* out = (float*)d_out;

    float *pq, *pk, *pv, *pat, *ptmp, *pz1, *pout;
    cudaGetSymbolAddress((void**)&pq,   g_q);
    cudaGetSymbolAddress((void**)&pk,   g_k);
    cudaGetSymbolAddress((void**)&pv,   g_v);
    cudaGetSymbolAddress((void**)&pat,  g_attn);
    cudaGetSymbolAddress((void**)&ptmp, g_tmp);
    cudaGetSymbolAddress((void**)&pz1,  g_z1);
    cudaGetSymbolAddress((void**)&pout, g_out);

    // 1) fused QKV on rolled input: [65536,512] x [512,256]^T  (x3 outputs)
    qkv_gemm<<<dim3(12, 512), 256>>>(x, Wq, Wk, Wv, bq, bk, bv, pq, pk, pv);

    // 2) window attention
    attn_kernel<<<16384, 128>>>();

    // 3) attention projection: [65536,256] x [256,512]^T
    sgemm_bias<<<dim3(8, 512), 256>>>(pat, aW, ab, ptmp, 512, 256);

    // 4) z1 = relu(x + roll(LN(zp), +2))
    ln_shift_add_relu<<<65536, 128>>>(ptmp, x, ag, abeta, pz1);

    // 5) FFN: [65536,512] x [512,512]^T
    sgemm_bias<<<dim3(8, 512), 256>>>(pz1, fW, fb, ptmp, 512, 512);

    // 6) out = relu(z1 + LN(y))
    ln_add_relu<<<65536, 128>>>(ptmp, pz1, fg, fbeta, pout);

    // 7/8) patch-merge GEMM: out viewed as [32768,1024] x [1024,512]^T
    sgemm_bias<<<dim3(8, 256), 256>>>(pout, dW, db, ptmp, 512, 1024);

    // 9) d_out = relu(LN(y2))
    ln_relu<<<32768, 128>>>(ptmp, dg, dbeta, out);
}

// round 9
// speedup vs baseline: 3.3422x; 1.6680x over previous
#include <cuda_runtime.h>
#include <cuda_bf16.h>
#include <math.h>
#include <stdint.h>

// ---------------------------------------------------------------------------
// ShiftWindowAttentionBlock  (B=32, M=8, P=256, D=512, H=4, A=64, WS=4, SH=2)
//
//   1) Q,K,V = roll(x,-2) @ W{q,k,v}^T + b    (fused bf16-split MMA GEMM)
//   2) window attention (WS=4, mask only on window 63: groups [1,1,2,2])
//   3) zp  = attn @ aW^T + ab                 (bf16-split MMA GEMM)
//   4) z1  = relu(x + roll(LN(zp), +2))       (fused row epilogue + split)
//   5) y   = z1 @ fW^T + fb                   (bf16-split MMA GEMM)
//   6) out = relu(z1 + LN(y))                 (fused row epilogue + split)
//   7) merged == out viewed as [32768, 1024]  (free reinterpret)
//   8) y2  = merged @ dW^T + db               (bf16-split MMA GEMM)
//   9) d_out = relu(LN(y2))                   (fused row epilogue)
//
// GEMM: mma.sync.m16n8k16 bf16 (plain PTX — the harness targets sm_103, which
// rejects tcgen05).  fp32 operands pre-split into hi/lo bf16:
//     D += Ah*Bh + Ah*Bl + Al*Bh    (fp32 accumulate, ~1e-5..1e-4 rel err)
// Packed bf16x2 k-pairs map natively onto the k16 fragment registers, so the
// R4 conflict-free XOR-swizzled double-buffered smem scheme is reused 1:1
// with "kpair" replacing "k" (half the LDS and MMA instructions of tf32-k8).
// ---------------------------------------------------------------------------

#define NTOK   65536          // B*M*P tokens

// ---- scratch (device globals: allocation-free per harness rules) ----------
__device__ float g_q   [NTOK * 256];
__device__ float g_k   [NTOK * 256];
__device__ float g_v   [NTOK * 256];
__device__ float g_tmp [NTOK * 512];
__device__ float g_z1  [NTOK * 512];

__device__ __nv_bfloat16 g_xh [NTOK * 512];
__device__ __nv_bfloat16 g_xl [NTOK * 512];
__device__ __nv_bfloat16 g_ath[NTOK * 256];
__device__ __nv_bfloat16 g_atl[NTOK * 256];
__device__ __nv_bfloat16 g_z1h[NTOK * 512];
__device__ __nv_bfloat16 g_z1l[NTOK * 512];
__device__ __nv_bfloat16 g_oh [NTOK * 512];
__device__ __nv_bfloat16 g_ol [NTOK * 512];

// packed weights hi/lo: wq | wk | wv | aW | fW | dW
#define OFF_WQ 0
#define OFF_WK 131072
#define OFF_WV 262144
#define OFF_AW 393216
#define OFF_FW 524288
#define OFF_DW 786432
#define W_TOTAL 1310720
__device__ __nv_bfloat16 g_wh[W_TOTAL];
__device__ __nv_bfloat16 g_wl[W_TOTAL];

// ---------------------------------------------------------------------------
// helpers
// ---------------------------------------------------------------------------
__device__ __forceinline__ void mma_bf16(float c[4], const uint32_t a[4],
                                         const uint32_t b[2])
{
    asm volatile(
        "mma.sync.aligned.m16n8k16.row.col.f32.bf16.bf16.f32 "
        "{%0,%1,%2,%3}, {%4,%5,%6,%7}, {%8,%9}, {%0,%1,%2,%3};"
        : "+f"(c[0]), "+f"(c[1]), "+f"(c[2]), "+f"(c[3])
        : "r"(a[0]), "r"(a[1]), "r"(a[2]), "r"(a[3]), "r"(b[0]), "r"(b[1]));
}

// bank-swizzle (R4-proven): psi(k) = (k&3)^(k>>2), phys col = col ^ (psi<<3)
__device__ __forceinline__ int swzA(int k, int col)
{
    return (k << 7) + (col ^ ((((k & 3) ^ (k >> 2))) << 3));
}
__device__ __forceinline__ int swzB(int k, int col)
{
    return (k << 6) + (col ^ ((((k & 3) ^ (k >> 2))) << 3));
}

__device__ __forceinline__ void bsplit(float x, __nv_bfloat16& h, __nv_bfloat16& l)
{
    h = __float2bfloat16(x);
    l = __float2bfloat16(x - __bfloat162float(h));
}
__device__ __forceinline__ uint32_t pack2(__nv_bfloat16 a, __nv_bfloat16 b)
{
    return ((uint32_t)__bfloat16_as_ushort(b) << 16) | __bfloat16_as_ushort(a);
}

// ---------------------------------------------------------------------------
// GEMM tile body: BM=128, BN=64, BK=32 bf16 (16 kpairs), 256 threads =
// 8 warps (4m x 2n), warp tile 32x32.  C[M,N] = A[M,K] @ W[N,K]^T + bias[N].
// A/W given as pre-split packed bf16 hi/lo arrays, K-contiguous rows.
// roll: A token-row gather p -> (p+2) mod 256 in the low 8 bits.
// ---------------------------------------------------------------------------
__device__ __forceinline__
void gemm_tile_bf16(const __nv_bfloat16* __restrict__ Ah, const __nv_bfloat16* __restrict__ Al,
                    const __nv_bfloat16* __restrict__ Wh, const __nv_bfloat16* __restrict__ Wl,
                    const float* __restrict__ bias, float* __restrict__ C,
                    int N, int K, int row0, int col0, bool roll)
{
    // [stage][16 kpairs][cols] packed bf16x2 words; 48 KB total
    __shared__ uint32_t As_h[2][16 * 128];
    __shared__ uint32_t As_l[2][16 * 128];
    __shared__ uint32_t Bs_h[2][16 * 64];
    __shared__ uint32_t Bs_l[2][16 * 64];

    const int tid  = threadIdx.x;
    const int lane = tid & 31;
    const int warp = tid >> 5;
    const int g    = lane >> 2;         // 0..7
    const int c    = lane & 3;          // 0..3
    const int wm   = (warp >> 1) * 32;  // warp m-origin
    const int wn   = (warp & 1) * 32;   // warp n-origin

    // ---- staging geometry (constant across k-loop) ----
    const int rA0 = tid >> 2;           // 0..63
    const int rA1 = rA0 + 64;           // 64..127
    const int c4  = tid & 3;            // uint4 index along k (8 bf16 each)
    int ar0 = row0 + rA0, ar1 = row0 + rA1;
    if (roll) {
        ar0 = (ar0 & ~255) | ((ar0 + 2) & 255);
        ar1 = (ar1 & ~255) | ((ar1 + 2) & 255);
    }
    const __nv_bfloat16* pA0h = Ah + (size_t)ar0 * K + c4 * 8;
    const __nv_bfloat16* pA0l = Al + (size_t)ar0 * K + c4 * 8;
    const __nv_bfloat16* pA1h = Ah + (size_t)ar1 * K + c4 * 8;
    const __nv_bfloat16* pA1l = Al + (size_t)ar1 * K + c4 * 8;
    const __nv_bfloat16* pBh  = Wh + (size_t)(col0 + rA0) * K + c4 * 8;
    const __nv_bfloat16* pBl  = Wl + (size_t)(col0 + rA0) * K + c4 * 8;

    int stA0[4], stA1[4], stB[4];       // swizzled store word-indices per j
#pragma unroll
    for (int j = 0; j < 4; j++) {
        const int kp = c4 * 4 + j;      // kpair index 0..15
        stA0[j] = swzA(kp, rA0);
        stA1[j] = swzA(kp, rA1);
        stB[j]  = swzB(kp, rA0);
    }

    float acc[2][4][4];
#pragma unroll
    for (int mi = 0; mi < 2; mi++)
#pragma unroll
        for (int nj = 0; nj < 4; nj++)
#pragma unroll
            for (int e = 0; e < 4; e++) acc[mi][nj][e] = 0.f;

    // ---- prologue: load + stage tile 0 ----
    uint4 a0h = *(const uint4*)(pA0h);
    uint4 a0l = *(const uint4*)(pA0l);
    uint4 a1h = *(const uint4*)(pA1h);
    uint4 a1l = *(const uint4*)(pA1l);
    uint4 bh  = *(const uint4*)(pBh);
    uint4 bl  = *(const uint4*)(pBl);
#pragma unroll
    for (int j = 0; j < 4; j++) {
        As_h[0][stA0[j]] = (&a0h.x)[j];  As_l[0][stA0[j]] = (&a0l.x)[j];
        As_h[0][stA1[j]] = (&a1h.x)[j];  As_l[0][stA1[j]] = (&a1l.x)[j];
        Bs_h[0][stB[j]]  = (&bh.x)[j];   Bs_l[0][stB[j]]  = (&bl.x)[j];
    }
    __syncthreads();

    int st = 0;
    for (int k0 = 0; k0 < K; k0 += 32) {
        const bool has_next = (k0 + 32 < K);
        if (has_next) {
            a0h = *(const uint4*)(pA0h + k0 + 32);
            a0l = *(const uint4*)(pA0l + k0 + 32);
            a1h = *(const uint4*)(pA1h + k0 + 32);
            a1l = *(const uint4*)(pA1l + k0 + 32);
            bh  = *(const uint4*)(pBh  + k0 + 32);
            bl  = *(const uint4*)(pBl  + k0 + 32);
        }

        // ---- compute current stage: 2 k16 steps (kpairs jb..jb+7) ----
#pragma unroll
        for (int half = 0; half < 2; half++) {
            const int jb = half * 8;
            uint32_t ah[2][4], al[2][4];
#pragma unroll
            for (int mi = 0; mi < 2; mi++) {
                const int m0 = wm + mi * 16;
                const int i00 = swzA(jb + c,     m0 + g);
                const int i01 = swzA(jb + c,     m0 + g + 8);
                const int i10 = swzA(jb + c + 4, m0 + g);
                const int i11 = swzA(jb + c + 4, m0 + g + 8);
                ah[mi][0] = As_h[st][i00];  al[mi][0] = As_l[st][i00];
                ah[mi][1] = As_h[st][i01];  al[mi][1] = As_l[st][i01];
                ah[mi][2] = As_h[st][i10];  al[mi][2] = As_l[st][i10];
                ah[mi][3] = As_h[st][i11];  al[mi][3] = As_l[st][i11];
            }
            uint32_t bhf[4][2], blf[4][2];
#pragma unroll
            for (int nj = 0; nj < 4; nj++) {
                const int n0 = wn + nj * 8;
                const int i0 = swzB(jb + c,     n0 + g);
                const int i1 = swzB(jb + c + 4, n0 + g);
                bhf[nj][0] = Bs_h[st][i0];  blf[nj][0] = Bs_l[st][i0];
                bhf[nj][1] = Bs_h[st][i1];  blf[nj][1] = Bs_l[st][i1];
            }
#pragma unroll
            for (int mi = 0; mi < 2; mi++)
#pragma unroll
                for (int nj = 0; nj < 4; nj++) {
                    mma_bf16(acc[mi][nj], ah[mi], bhf[nj]);
                    mma_bf16(acc[mi][nj], ah[mi], blf[nj]);
                    mma_bf16(acc[mi][nj], al[mi], bhf[nj]);
                }
        }

        // ---- stage next tile into the other buffer ----
        if (has_next) {
            const int ns = st ^ 1;
#pragma unroll
            for (int j = 0; j < 4; j++) {
                As_h[ns][stA0[j]] = (&a0h.x)[j];  As_l[ns][stA0[j]] = (&a0l.x)[j];
                As_h[ns][stA1[j]] = (&a1h.x)[j];  As_l[ns][stA1[j]] = (&a1l.x)[j];
                Bs_h[ns][stB[j]]  = (&bh.x)[j];   Bs_l[ns][stB[j]]  = (&bl.x)[j];
            }
        }
        __syncthreads();
        st ^= 1;
    }

    // ---- epilogue: add bias, store (float2 per C-frag row pair) ----
#pragma unroll
    for (int mi = 0; mi < 2; mi++)
#pragma unroll
        for (int nj = 0; nj < 4; nj++) {
            const int gc = col0 + wn + nj * 8 + 2 * c;
            const float bx = bias[gc], by = bias[gc + 1];
            {
                const size_t gr = (size_t)(row0 + wm + mi * 16 + g);
                float2 o; o.x = acc[mi][nj][0] + bx; o.y = acc[mi][nj][1] + by;
                *(float2*)(C + gr * N + gc) = o;
            }
            {
                const size_t gr = (size_t)(row0 + wm + mi * 16 + g + 8);
                float2 o; o.x = acc[mi][nj][2] + bx; o.y = acc[mi][nj][3] + by;
                *(float2*)(C + gr * N + gc) = o;
            }
        }
}

// generic GEMM (no roll)
__global__ __launch_bounds__(256, 2)
void hgemm_bias(const __nv_bfloat16* __restrict__ Ah, const __nv_bfloat16* __restrict__ Al,
                const __nv_bfloat16* __restrict__ Wh, const __nv_bfloat16* __restrict__ Wl,
                const float* __restrict__ bias, float* __restrict__ C, int N, int K)
{
    gemm_tile_bf16(Ah, Al, Wh, Wl, bias, C, N, K,
                   blockIdx.y * 128, blockIdx.x * 64, false);
}

// fused QKV GEMM with rolled A-gather: blockIdx.x = sel*4 + n-tile
__global__ __launch_bounds__(256, 2)
void hgemm_qkv(const __nv_bfloat16* __restrict__ xh, const __nv_bfloat16* __restrict__ xl,
               const __nv_bfloat16* __restrict__ wh, const __nv_bfloat16* __restrict__ wl,
               const float* __restrict__ bq, const float* __restrict__ bk,
               const float* __restrict__ bv,
               float* __restrict__ q, float* __restrict__ k, float* __restrict__ v)
{
    const int sel  = blockIdx.x >> 2;
    const int col0 = (blockIdx.x & 3) * 64;
    const __nv_bfloat16* Wh = wh + sel * 131072;
    const __nv_bfloat16* Wl = wl + sel * 131072;
    const float* bias = (sel == 0) ? bq : (sel == 1) ? bk : bv;
    float*       out  = (sel == 0) ? q  : (sel == 1) ? k  : v;
    gemm_tile_bf16(xh, xl, Wh, Wl, bias, out, 256, 512, blockIdx.y * 128, col0, true);
}

// ---------------------------------------------------------------------------
// hi/lo pre-split kernels
// ---------------------------------------------------------------------------
__global__ __launch_bounds__(256)
void split_x_kernel(const float* __restrict__ x,
                    __nv_bfloat16* __restrict__ xh, __nv_bfloat16* __restrict__ xl)
{
    const size_t i = (size_t)blockIdx.x * 256 + threadIdx.x;   // float4 index
    const float4 v = ((const float4*)x)[i];
    __nv_bfloat16 h0, h1, h2, h3, l0, l1, l2, l3;
    bsplit(v.x, h0, l0); bsplit(v.y, h1, l1);
    bsplit(v.z, h2, l2); bsplit(v.w, h3, l3);
    uint2 uh; uh.x = pack2(h0, h1); uh.y = pack2(h2, h3);
    uint2 ul; ul.x = pack2(l0, l1); ul.y = pack2(l2, l3);
    *(uint2*)(xh + 4 * i) = uh;
    *(uint2*)(xl + 4 * i) = ul;
}

__global__ __launch_bounds__(256)
void split_w_kernel(const float* __restrict__ Wq, const float* __restrict__ Wk,
                    const float* __restrict__ Wv, const float* __restrict__ aW,
                    const float* __restrict__ fW, const float* __restrict__ dW,
                    __nv_bfloat16* __restrict__ wh, __nv_bfloat16* __restrict__ wl)
{
    const int idx = blockIdx.x * 256 + threadIdx.x;
    float v;
    if      (idx < OFF_WK) v = Wq[idx - OFF_WQ];
    else if (idx < OFF_WV) v = Wk[idx - OFF_WK];
    else if (idx < OFF_AW) v = Wv[idx - OFF_WV];
    else if (idx < OFF_FW) v = aW[idx - OFF_AW];
    else if (idx < OFF_DW) v = fW[idx - OFF_FW];
    else                   v = dW[idx - OFF_DW];
    __nv_bfloat16 h, l;
    bsplit(v, h, l);
    wh[idx] = h; wl[idx] = l;
}

// ---------------------------------------------------------------------------
// Window attention: one block per window (4 tokens), one warp per head.
// Emits hi/lo bf16 directly (feeds the proj GEMM).
// ---------------------------------------------------------------------------
__global__ __launch_bounds__(128)
void attn_kernel()
{
    const int wg   = blockIdx.x;
    const int h    = threadIdx.x >> 5;
    const int lane = threadIdx.x & 31;
    const size_t base = (size_t)(wg << 2) * 256 + h * 64 + lane;

    float qf0[4], qf1[4], kf0[4], kf1[4], vf0[4], vf1[4];
#pragma unroll
    for (int i = 0; i < 4; i++) {
        qf0[i] = g_q[base + i * 256];  qf1[i] = g_q[base + i * 256 + 32];
        kf0[i] = g_k[base + i * 256];  kf1[i] = g_k[base + i * 256 + 32];
        vf0[i] = g_v[base + i * 256];  vf1[i] = g_v[base + i * 256 + 32];
    }

    const bool masked = ((wg & 63) == 63);

    float s[4][4];
#pragma unroll
    for (int i = 0; i < 4; i++)
#pragma unroll
        for (int j = 0; j < 4; j++) {
            float p = qf0[i] * kf0[j] + qf1[i] * kf1[j];
#pragma unroll
            for (int off = 16; off; off >>= 1)
                p += __shfl_xor_sync(0xffffffffu, p, off);
            const float m = (masked && ((i < 2) != (j < 2))) ? -100.f : 0.f;
            s[i][j] = p * 0.125f + m;   // 1/sqrt(64)
        }

#pragma unroll
    for (int i = 0; i < 4; i++) {
        const float mx = fmaxf(fmaxf(s[i][0], s[i][1]), fmaxf(s[i][2], s[i][3]));
        const float e0 = expf(s[i][0] - mx);
        const float e1 = expf(s[i][1] - mx);
        const float e2 = expf(s[i][2] - mx);
        const float e3 = expf(s[i][3] - mx);
        const float inv = 1.f / (e0 + e1 + e2 + e3);
        const float o0 = (e0 * vf0[0] + e1 * vf0[1] + e2 * vf0[2] + e3 * vf0[3]) * inv;
        const float o1 = (e0 * vf1[0] + e1 * vf1[1] + e2 * vf1[2] + e3 * vf1[3]) * inv;
        __nv_bfloat16 hh, ll;
        bsplit(o0, hh, ll);
        g_ath[base + i * 256] = hh;  g_atl[base + i * 256] = ll;
        bsplit(o1, hh, ll);
        g_ath[base + i * 256 + 32] = hh;  g_atl[base + i * 256 + 32] = ll;
    }
}

// ---------------------------------------------------------------------------
// Row epilogues: 1 block (128 threads) per row of 512, 4 elems per thread.
// ---------------------------------------------------------------------------
__device__ __forceinline__ float2 block_sum2_128(float s1, float s2)
{
#pragma unroll
    for (int off = 16; off; off >>= 1) {
        s1 += __shfl_xor_sync(0xffffffffu, s1, off);
        s2 += __shfl_xor_sync(0xffffffffu, s2, off);
    }
    __shared__ float sh[8];
    const int w = threadIdx.x >> 5;
    if ((threadIdx.x & 31) == 0) { sh[w] = s1; sh[w + 4] = s2; }
    __syncthreads();
    return make_float2(sh[0] + sh[1] + sh[2] + sh[3],
                       sh[4] + sh[5] + sh[6] + sh[7]);
}

// z1 = relu(x + roll(LN(zp), +2));  writes z1 fp32 AND z1 hi/lo bf16
__global__ __launch_bounds__(128)
void ln_shift_add_relu(const float* __restrict__ zp, const float* __restrict__ x,
                       const float* __restrict__ g, const float* __restrict__ b,
                       float* __restrict__ z1,
                       __nv_bfloat16* __restrict__ z1h, __nv_bfloat16* __restrict__ z1l)
{
    const size_t row = blockIdx.x;
    const int    c   = threadIdx.x * 4;
    const float4 v   = *(const float4*)(zp + row * 512 + c);
    float2 ss = block_sum2_128(v.x + v.y + v.z + v.w,
                               v.x * v.x + v.y * v.y + v.z * v.z + v.w * v.w);
    const float mu   = ss.x * (1.f / 512.f);
    const float var  = ss.y * (1.f / 512.f) - mu * mu;
    const float rstd = rsqrtf(var + 1e-5f);

    const size_t orow = (row & ~(size_t)255) | ((row + 2) & 255);
    const float4 gg = *(const float4*)(g + c);
    const float4 bb = *(const float4*)(b + c);
    const float4 xv = *(const float4*)(x + orow * 512 + c);
    float4 o;
    o.x = fmaxf(xv.x + (v.x - mu) * rstd * gg.x + bb.x, 0.f);
    o.y = fmaxf(xv.y + (v.y - mu) * rstd * gg.y + bb.y, 0.f);
    o.z = fmaxf(xv.z + (v.z - mu) * rstd * gg.z + bb.z, 0.f);
    o.w = fmaxf(xv.w + (v.w - mu) * rstd * gg.w + bb.w, 0.f);
    *(float4*)(z1 + orow * 512 + c) = o;

    __nv_bfloat16 h0, h1, h2, h3, l0, l1, l2, l3;
    bsplit(o.x, h0, l0); bsplit(o.y, h1, l1);
    bsplit(o.z, h2, l2); bsplit(o.w, h3, l3);
    uint2 uh; uh.x = pack2(h0, h1); uh.y = pack2(h2, h3);
    uint2 ul; ul.x = pack2(l0, l1); ul.y = pack2(l2, l3);
    *(uint2*)(z1h + orow * 512 + c) = uh;
    *(uint2*)(z1l + orow * 512 + c) = ul;
}

// out = relu(z1 + LN(y)); writes ONLY hi/lo bf16 (feeds merge GEMM)
__global__ __launch_bounds__(128)
void ln_add_relu(const float* __restrict__ y, const float* __restrict__ z1,
                 const float* __restrict__ g, const float* __restrict__ b,
                 __nv_bfloat16* __restrict__ oh, __nv_bfloat16* __restrict__ ol)
{
    const size_t row = blockIdx.x;
    const int    c   = threadIdx.x * 4;
    const float4 v   = *(const float4*)(y + row * 512 + c);
    float2 ss = block_sum2_128(v.x + v.y + v.z + v.w,
                               v.x * v.x + v.y * v.y + v.z * v.z + v.w * v.w);
    const float mu   = ss.x * (1.f / 512.f);
    const float var  = ss.y * (1.f / 512.f) - mu * mu;
    const float rstd = rsqrtf(var + 1e-5f);

    const float4 gg = *(const float4*)(g + c);
    const float4 bb = *(const float4*)(b + c);
    const float4 zv = *(const float4*)(z1 + row * 512 + c);
    float4 o;
    o.x = fmaxf(zv.x + (v.x - mu) * rstd * gg.x + bb.x, 0.f);
    o.y = fmaxf(zv.y + (v.y - mu) * rstd * gg.y + bb.y, 0.f);
    o.z = fmaxf(zv.z + (v.z - mu) * rstd * gg.z + bb.z, 0.f);
    o.w = fmaxf(zv.w + (v.w - mu) * rstd * gg.w + bb.w, 0.f);

    __nv_bfloat16 h0, h1, h2, h3, l0, l1, l2, l3;
    bsplit(o.x, h0, l0); bsplit(o.y, h1, l1);
    bsplit(o.z, h2, l2); bsplit(o.w, h3, l3);
    uint2 uh; uh.x = pack2(h0, h1); uh.y = pack2(h2, h3);
    uint2 ul; ul.x = pack2(l0, l1); ul.y = pack2(l2, l3);
    *(uint2*)(oh + row * 512 + c) = uh;
    *(uint2*)(ol + row * 512 + c) = ul;
}

// d_out = relu(LN(y2))
__global__ __launch_bounds__(128)
void ln_relu(const float* __restrict__ y, const float* __restrict__ g,
             const float* __restrict__ b, float* __restrict__ out)
{
    const size_t row = blockIdx.x;
    const int    c   = threadIdx.x * 4;
    const float4 v   = *(const float4*)(y + row * 512 + c);
    float2 ss = block_sum2_128(v.x + v.y + v.z + v.w,
                               v.x * v.x + v.y * v.y + v.z * v.z + v.w * v.w);
    const float mu   = ss.x * (1.f / 512.f);
    const float var  = ss.y * (1.f / 512.f) - mu * mu;
    const float rstd = rsqrtf(var + 1e-5f);

    const float4 gg = *(const float4*)(g + c);
    const float4 bb = *(const float4*)(b + c);
    float4 o;
    o.x = fmaxf((v.x - mu) * rstd * gg.x + bb.x, 0.f);
    o.y = fmaxf((v.y - mu) * rstd * gg.y + bb.y, 0.f);
    o.z = fmaxf((v.z - mu) * rstd * gg.z + bb.z, 0.f);
    o.w = fmaxf((v.w - mu) * rstd * gg.w + bb.w, 0.f);
    *(float4*)(out + row * 512 + c) = o;
}

// ---------------------------------------------------------------------------
extern "C" void kernel_launch(void* const* d_in, const int* in_sizes, int n_in,
                              void* d_out, int out_size)
{
    const float* x     = (const float*)d_in[0];
    const float* Wq    = (const float*)d_in[1];
    const float* bq    = (const float*)d_in[2];
    const float* Wk    = (const float*)d_in[3];
    const float* bk    = (const float*)d_in[4];
    const float* Wv    = (const float*)d_in[5];
    const float* bv    = (const float*)d_in[6];
    const float* aW    = (const float*)d_in[7];
    const float* ab    = (const float*)d_in[8];
    const float* ag    = (const float*)d_in[9];
    const float* abeta = (const float*)d_in[10];
    const float* fW    = (const float*)d_in[11];
    const float* fb    = (const float*)d_in[12];
    const float* fg    = (const float*)d_in[13];
    const float* fbeta = (const float*)d_in[14];
    const float* dW    = (const float*)d_in[15];
    const float* db    = (const float*)d_in[16];
    const float* dg    = (const float*)d_in[17];
    const float* dbeta = (const float*)d_in[18];
    float* out = (float*)d_out;

    float *pq, *pk, *pv, *ptmp, *pz1;
    __nv_bfloat16 *pxh, *pxl, *path, *patl, *pz1h, *pz1l, *poh, *pol, *pwh, *pwl;
    cudaGetSymbolAddress((void**)&pq,   g_q);
    cudaGetSymbolAddress((void**)&pk,   g_k);
    cudaGetSymbolAddress((void**)&pv,   g_v);
    cudaGetSymbolAddress((void**)&ptmp, g_tmp);
    cudaGetSymbolAddress((void**)&pz1,  g_z1);
    cudaGetSymbolAddress((void**)&pxh,  g_xh);
    cudaGetSymbolAddress((void**)&pxl,  g_xl);
    cudaGetSymbolAddress((void**)&path, g_ath);
    cudaGetSymbolAddress((void**)&patl, g_atl);
    cudaGetSymbolAddress((void**)&pz1h, g_z1h);
    cudaGetSymbolAddress((void**)&pz1l, g_z1l);
    cudaGetSymbolAddress((void**)&poh,  g_oh);
    cudaGetSymbolAddress((void**)&pol,  g_ol);
    cudaGetSymbolAddress((void**)&pwh,  g_wh);
    cudaGetSymbolAddress((void**)&pwl,  g_wl);

    // 0) pre-split operands to bf16 hi/lo
    split_x_kernel<<<32768, 256>>>(x, pxh, pxl);
    split_w_kernel<<<5120, 256>>>(Wq, Wk, Wv, aW, fW, dW, pwh, pwl);

    // 1) fused QKV on rolled input: [65536,512] x [512,256]^T (x3 outputs)
    hgemm_qkv<<<dim3(12, 512), 256>>>(pxh, pxl, pwh, pwl, bq, bk, bv, pq, pk, pv);

    // 2) window attention (emits hi/lo bf16)
    attn_kernel<<<16384, 128>>>();

    // 3) attention projection: [65536,256] x [256,512]^T
    hgemm_bias<<<dim3(8, 512), 256>>>(path, patl, pwh + OFF_AW, pwl + OFF_AW,
                                      ab, ptmp, 512, 256);

    // 4) z1 = relu(x + roll(LN(zp), +2))  (+ hi/lo split)
    ln_shift_add_relu<<<65536, 128>>>(ptmp, x, ag, abeta, pz1, pz1h, pz1l);

    // 5) FFN: [65536,512] x [512,512]^T
    hgemm_bias<<<dim3(8, 512), 256>>>(pz1h, pz1l, pwh + OFF_FW, pwl + OFF_FW,
                                      fb, ptmp, 512, 512);

    // 6) out = relu(z1 + LN(y))  (hi/lo only; feeds merge GEMM)
    ln_add_relu<<<65536, 128>>>(ptmp, pz1, fg, fbeta, poh, pol);

    // 7/8) patch-merge GEMM: out viewed as [32768,1024] x [1024,512]^T
    hgemm_bias<<<dim3(8, 256), 256>>>(poh, pol, pwh + OFF_DW, pwl + OFF_DW,
                                      db, ptmp, 512, 1024);

    // 9) d_out = relu(LN(y2))
    ln_relu<<<32768, 128>>>(ptmp, dg, dbeta, out);
}

// round 14
// speedup vs baseline: 3.9274x; 1.1751x over previous
#include <cuda_runtime.h>
#include <cuda_bf16.h>
#include <math.h>
#include <stdint.h>

// ---------------------------------------------------------------------------
// ShiftWindowAttentionBlock  (B=32, M=8, P=256, D=512, H=4, A=64, WS=4, SH=2)
//
// GEMMs: mma.sync.m16n8k16 bf16 with 3-term hi/lo split (hh + hl + lh),
// fp32 accumulate (~7e-6 rel err measured).  v3 pipeline:
//   - cp.async 16B (LDGSTS), 3-stage ring, commit/wait groups
//   - ldmatrix.x4 fragment loads (4x fewer shared-pipe instructions)
//   - K-major smem rows: 64B data + 16B pad (stride 20 words) ->
//     conflict-free cp.async stores AND ldmatrix phases.
// ---------------------------------------------------------------------------

#define NTOK   65536          // B*M*P tokens

// ---- scratch (device globals: allocation-free per harness rules) ----------
__device__ float g_q   [NTOK * 256];
__device__ float g_k   [NTOK * 256];
__device__ float g_v   [NTOK * 256];
__device__ float g_tmp [NTOK * 512];
__device__ float g_z1  [NTOK * 512];

__device__ __nv_bfloat16 g_xh [NTOK * 512];
__device__ __nv_bfloat16 g_xl [NTOK * 512];
__device__ __nv_bfloat16 g_ath[NTOK * 256];
__device__ __nv_bfloat16 g_atl[NTOK * 256];
__device__ __nv_bfloat16 g_z1h[NTOK * 512];
__device__ __nv_bfloat16 g_z1l[NTOK * 512];
__device__ __nv_bfloat16 g_oh [NTOK * 512];
__device__ __nv_bfloat16 g_ol [NTOK * 512];

// packed weights hi/lo: wq | wk | wv | aW | fW | dW
#define OFF_WQ 0
#define OFF_WK 131072
#define OFF_WV 262144
#define OFF_AW 393216
#define OFF_FW 524288
#define OFF_DW 786432
#define W_TOTAL 1310720
__device__ __nv_bfloat16 g_wh[W_TOTAL];
__device__ __nv_bfloat16 g_wl[W_TOTAL];

// ---------------------------------------------------------------------------
// helpers
// ---------------------------------------------------------------------------
__device__ __forceinline__ void mma_bf16(float c[4], const uint32_t a[4],
                                         const uint32_t b[2])
{
    asm volatile(
        "mma.sync.aligned.m16n8k16.row.col.f32.bf16.bf16.f32 "
        "{%0,%1,%2,%3}, {%4,%5,%6,%7}, {%8,%9}, {%0,%1,%2,%3};"
        : "+f"(c[0]), "+f"(c[1]), "+f"(c[2]), "+f"(c[3])
        : "r"(a[0]), "r"(a[1]), "r"(a[2]), "r"(a[3]), "r"(b[0]), "r"(b[1]));
}

__device__ __forceinline__ void ldsm4(uint32_t r[4], uint32_t addr)
{
    asm volatile("ldmatrix.sync.aligned.m8n8.x4.shared.b16 {%0,%1,%2,%3}, [%4];"
                 : "=r"(r[0]), "=r"(r[1]), "=r"(r[2]), "=r"(r[3]) : "r"(addr));
}

__device__ __forceinline__ void cpasync16(uint32_t saddr, const void* g)
{
    asm volatile("cp.async.cg.shared.global [%0], [%1], 16;"
                 :: "r"(saddr), "l"(g) : "memory");
}
#define CP_COMMIT() asm volatile("cp.async.commit_group;" ::: "memory")
#define CP_WAIT1()  asm volatile("cp.async.wait_group 1;" ::: "memory")
#define CP_WAIT0()  asm volatile("cp.async.wait_group 0;" ::: "memory")

__device__ __forceinline__ void bsplit(float x, __nv_bfloat16& h, __nv_bfloat16& l)
{
    h = __float2bfloat16(x);
    l = __float2bfloat16(x - __bfloat162float(h));
}
__device__ __forceinline__ uint32_t pack2(__nv_bfloat16 a, __nv_bfloat16 b)
{
    return ((uint32_t)__bfloat16_as_ushort(b) << 16) | __bfloat16_as_ushort(a);
}

// ---------------------------------------------------------------------------
// GEMM v3: BM=128, BN=64, BK=32 bf16, 256 threads = 8 warps (4m x 2n),
// warp tile 32x32.  C[M,N] = A[M,K] @ W[N,K]^T + bias[N].
//
// smem stage layout (bytes, per stage; row = 64B K-data + 16B pad = 80B):
//   Ah @ 0      (128 rows x 80 = 10240)
//   Al @ 10240
//   Bh @ 20480  (64 rows x 80 = 5120)
//   Bl @ 25600
//   stage stride 30720; 3 stages = 92160 dynamic smem.
// ---------------------------------------------------------------------------
#define STAGE_B  30720
#define N_STAGE  3
#define SMEM_GEMM (N_STAGE * STAGE_B)

__device__ __forceinline__
void gemm_tile_bf16(const __nv_bfloat16* __restrict__ Ah, const __nv_bfloat16* __restrict__ Al,
                    const __nv_bfloat16* __restrict__ Wh, const __nv_bfloat16* __restrict__ Wl,
                    const float* __restrict__ bias, float* __restrict__ C,
                    int N, int K, int row0, int col0, bool roll)
{
    extern __shared__ char dsm[];
    const uint32_t sm0 = (uint32_t)__cvta_generic_to_shared(dsm);

    const int tid  = threadIdx.x;
    const int lane = tid & 31;
    const int warp = tid >> 5;
    const int g    = lane >> 2;         // 0..7
    const int c    = lane & 3;          // 0..3
    const int wm   = (warp >> 1) * 32;  // warp m-origin
    const int wn   = (warp & 1) * 32;   // warp n-origin

    // ---- staging geometry ----
    const int rA0 = tid >> 2;           // 0..63
    const int rA1 = rA0 + 64;           // 64..127
    const int c4  = tid & 3;            // 16B chunk along K (8 bf16)
    int ar0 = row0 + rA0, ar1 = row0 + rA1;
    if (roll) {
        ar0 = (ar0 & ~255) | ((ar0 + 2) & 255);
        ar1 = (ar1 & ~255) | ((ar1 + 2) & 255);
    }
    const __nv_bfloat16* pA0h = Ah + (size_t)ar0 * K + c4 * 8;
    const __nv_bfloat16* pA0l = Al + (size_t)ar0 * K + c4 * 8;
    const __nv_bfloat16* pA1h = Ah + (size_t)ar1 * K + c4 * 8;
    const __nv_bfloat16* pA1l = Al + (size_t)ar1 * K + c4 * 8;
    const __nv_bfloat16* pBh  = Wh + (size_t)(col0 + rA0) * K + c4 * 8;
    const __nv_bfloat16* pBl  = Wl + (size_t)(col0 + rA0) * K + c4 * 8;

    const uint32_t sA0 = (uint32_t)(rA0 * 80 + c4 * 16);
    const uint32_t sA1 = (uint32_t)(rA1 * 80 + c4 * 16);
    const uint32_t sB  = (uint32_t)(rA0 * 80 + c4 * 16);

    // ---- ldmatrix per-lane byte offsets (within region) ----
    // A .x4: tiles (rows0-7,chunk0)(rows8-15,chunk0)(rows0-7,chunk1)(rows8-15,chunk1)
    const uint32_t aoff = (uint32_t)((wm + (lane & 7) + ((lane >> 3) & 1) * 8) * 80
                                     + (lane >> 4) * 16);
    // B .x4: tiles (nj,chunk0)(nj,chunk1)(nj+1,chunk0)(nj+1,chunk1)
    const uint32_t boff = (uint32_t)((wn + (lane >> 4) * 8 + (lane & 7)) * 80
                                     + ((lane >> 3) & 1) * 16);

    float acc[2][4][4];
#pragma unroll
    for (int mi = 0; mi < 2; mi++)
#pragma unroll
        for (int nj = 0; nj < 4; nj++)
#pragma unroll
            for (int e = 0; e < 4; e++) acc[mi][nj][e] = 0.f;

    const int KT = K >> 5;

    // ---- prologue: stage tiles 0 and 1 ----
#pragma unroll
    for (int p = 0; p < N_STAGE - 1; p++) {
        const uint32_t sb = sm0 + (uint32_t)p * STAGE_B;
        const int ke = p * 32;
        cpasync16(sb + sA0,          pA0h + ke);
        cpasync16(sb + sA1,          pA1h + ke);
        cpasync16(sb + 10240u + sA0, pA0l + ke);
        cpasync16(sb + 10240u + sA1, pA1l + ke);
        cpasync16(sb + 20480u + sB,  pBh + ke);
        cpasync16(sb + 25600u + sB,  pBl + ke);
        CP_COMMIT();
    }

    int slot = 0;
    for (int kt = 0; kt < KT; kt++) {
        if (kt == KT - 1) { CP_WAIT0(); } else { CP_WAIT1(); }
        __syncthreads();

        // stage tile kt+2 into the slot computed at iter kt-1 (all warps past barrier)
        if (kt + N_STAGE - 1 < KT) {
            const int ps = kt + N_STAGE - 1;
            const uint32_t sb = sm0 + (uint32_t)(ps % N_STAGE) * STAGE_B;
            const int ke = ps * 32;
            cpasync16(sb + sA0,          pA0h + ke);
            cpasync16(sb + sA1,          pA1h + ke);
            cpasync16(sb + 10240u + sA0, pA0l + ke);
            cpasync16(sb + 10240u + sA1, pA1l + ke);
            cpasync16(sb + 20480u + sB,  pBh + ke);
            cpasync16(sb + 25600u + sB,  pBl + ke);
            CP_COMMIT();
        }

        // ---- compute current stage: 2 k16 halves ----
        const uint32_t sb = sm0 + (uint32_t)slot * STAGE_B;
#pragma unroll
        for (int h2 = 0; h2 < 2; h2++) {
            const uint32_t kb = sb + (uint32_t)(h2 * 32);
            uint32_t ahf[2][4], alf[2][4], bhf[2][4], blf[2][4];
            ldsm4(ahf[0], kb + aoff);
            ldsm4(ahf[1], kb + aoff + 1280u);            // mi=1 (+16 rows)
            ldsm4(alf[0], kb + 10240u + aoff);
            ldsm4(alf[1], kb + 10240u + aoff + 1280u);
            ldsm4(bhf[0], kb + 20480u + boff);
            ldsm4(bhf[1], kb + 20480u + boff + 1280u);   // njpair=1 (+16 rows)
            ldsm4(blf[0], kb + 25600u + boff);
            ldsm4(blf[1], kb + 25600u + boff + 1280u);
#pragma unroll
            for (int mi = 0; mi < 2; mi++)
#pragma unroll
                for (int nj = 0; nj < 4; nj++) {
                    const int p  = nj >> 1;
                    const int e  = (nj & 1) * 2;
                    uint32_t bh2[2] = { bhf[p][e], bhf[p][e + 1] };
                    uint32_t bl2[2] = { blf[p][e], blf[p][e + 1] };
                    mma_bf16(acc[mi][nj], ahf[mi], bh2);
                    mma_bf16(acc[mi][nj], ahf[mi], bl2);
                    mma_bf16(acc[mi][nj], alf[mi], bh2);
                }
        }
        slot = (slot + 1 == N_STAGE) ? 0 : slot + 1;
        __syncthreads();
    }

    // ---- epilogue: add bias, store (float2 per C-frag row pair) ----
#pragma unroll
    for (int mi = 0; mi < 2; mi++)
#pragma unroll
        for (int nj = 0; nj < 4; nj++) {
            const int gc = col0 + wn + nj * 8 + 2 * c;
            const float bx = bias[gc], by = bias[gc + 1];
            {
                const size_t gr = (size_t)(row0 + wm + mi * 16 + g);
                float2 o; o.x = acc[mi][nj][0] + bx; o.y = acc[mi][nj][1] + by;
                *(float2*)(C + gr * N + gc) = o;
            }
            {
                const size_t gr = (size_t)(row0 + wm + mi * 16 + g + 8);
                float2 o; o.x = acc[mi][nj][2] + bx; o.y = acc[mi][nj][3] + by;
                *(float2*)(C + gr * N + gc) = o;
            }
        }
}

// generic GEMM (no roll)
__global__ __launch_bounds__(256, 2)
void hgemm_bias(const __nv_bfloat16* __restrict__ Ah, const __nv_bfloat16* __restrict__ Al,
                const __nv_bfloat16* __restrict__ Wh, const __nv_bfloat16* __restrict__ Wl,
                const float* __restrict__ bias, float* __restrict__ C, int N, int K)
{
    gemm_tile_bf16(Ah, Al, Wh, Wl, bias, C, N, K,
                   blockIdx.y * 128, blockIdx.x * 64, false);
}

// fused QKV GEMM with rolled A-gather: blockIdx.x = sel*4 + n-tile
__global__ __launch_bounds__(256, 2)
void hgemm_qkv(const __nv_bfloat16* __restrict__ xh, const __nv_bfloat16* __restrict__ xl,
               const __nv_bfloat16* __restrict__ wh, const __nv_bfloat16* __restrict__ wl,
               const float* __restrict__ bq, const float* __restrict__ bk,
               const float* __restrict__ bv,
               float* __restrict__ q, float* __restrict__ k, float* __restrict__ v)
{
    const int sel  = blockIdx.x >> 2;
    const int col0 = (blockIdx.x & 3) * 64;
    const __nv_bfloat16* Wh = wh + sel * 131072;
    const __nv_bfloat16* Wl = wl + sel * 131072;
    const float* bias = (sel == 0) ? bq : (sel == 1) ? bk : bv;
    float*       out  = (sel == 0) ? q  : (sel == 1) ? k  : v;
    gemm_tile_bf16(xh, xl, Wh, Wl, bias, out, 256, 512, blockIdx.y * 128, col0, true);
}

// ---------------------------------------------------------------------------
// hi/lo pre-split kernels
// ---------------------------------------------------------------------------
__global__ __launch_bounds__(256)
void split_x_kernel(const float* __restrict__ x,
                    __nv_bfloat16* __restrict__ xh, __nv_bfloat16* __restrict__ xl)
{
    const size_t i = (size_t)blockIdx.x * 256 + threadIdx.x;   // float4 index
    const float4 v = ((const float4*)x)[i];
    __nv_bfloat16 h0, h1, h2, h3, l0, l1, l2, l3;
    bsplit(v.x, h0, l0); bsplit(v.y, h1, l1);
    bsplit(v.z, h2, l2); bsplit(v.w, h3, l3);
    uint2 uh; uh.x = pack2(h0, h1); uh.y = pack2(h2, h3);
    uint2 ul; ul.x = pack2(l0, l1); ul.y = pack2(l2, l3);
    *(uint2*)(xh + 4 * i) = uh;
    *(uint2*)(xl + 4 * i) = ul;
}

__global__ __launch_bounds__(256)
void split_w_kernel(const float* __restrict__ Wq, const float* __restrict__ Wk,
                    const float* __restrict__ Wv, const float* __restrict__ aW,
                    const float* __restrict__ fW, const float* __restrict__ dW,
                    __nv_bfloat16* __restrict__ wh, __nv_bfloat16* __restrict__ wl)
{
    const int idx = blockIdx.x * 256 + threadIdx.x;
    float v;
    if      (idx < OFF_WK) v = Wq[idx - OFF_WQ];
    else if (idx < OFF_WV) v = Wk[idx - OFF_WK];
    else if (idx < OFF_AW) v = Wv[idx - OFF_WV];
    else if (idx < OFF_FW) v = aW[idx - OFF_AW];
    else if (idx < OFF_DW) v = fW[idx - OFF_FW];
    else                   v = dW[idx - OFF_DW];
    __nv_bfloat16 h, l;
    bsplit(v, h, l);
    wh[idx] = h; wl[idx] = l;
}

// ---------------------------------------------------------------------------
// Window attention: one block per window (4 tokens), one warp per head.
// Emits hi/lo bf16 directly (feeds the proj GEMM).
// ---------------------------------------------------------------------------
__global__ __launch_bounds__(128)
void attn_kernel()
{
    const int wg   = blockIdx.x;
    const int h    = threadIdx.x >> 5;
    const int lane = threadIdx.x & 31;
    const size_t base = (size_t)(wg << 2) * 256 + h * 64 + lane;

    float qf0[4], qf1[4], kf0[4], kf1[4], vf0[4], vf1[4];
#pragma unroll
    for (int i = 0; i < 4; i++) {
        qf0[i] = g_q[base + i * 256];  qf1[i] = g_q[base + i * 256 + 32];
        kf0[i] = g_k[base + i * 256];  kf1[i] = g_k[base + i * 256 + 32];
        vf0[i] = g_v[base + i * 256];  vf1[i] = g_v[base + i * 256 + 32];
    }

    const bool masked = ((wg & 63) == 63);

    float s[4][4];
#pragma unroll
    for (int i = 0; i < 4; i++)
#pragma unroll
        for (int j = 0; j < 4; j++) {
            float p = qf0[i] * kf0[j] + qf1[i] * kf1[j];
#pragma unroll
            for (int off = 16; off; off >>= 1)
                p += __shfl_xor_sync(0xffffffffu, p, off);
            const float m = (masked && ((i < 2) != (j < 2))) ? -100.f : 0.f;
            s[i][j] = p * 0.125f + m;   // 1/sqrt(64)
        }

#pragma unroll
    for (int i = 0; i < 4; i++) {
        const float mx = fmaxf(fmaxf(s[i][0], s[i][1]), fmaxf(s[i][2], s[i][3]));
        const float e0 = expf(s[i][0] - mx);
        const float e1 = expf(s[i][1] - mx);
        const float e2 = expf(s[i][2] - mx);
        const float e3 = expf(s[i][3] - mx);
        const float inv = 1.f / (e0 + e1 + e2 + e3);
        const float o0 = (e0 * vf0[0] + e1 * vf0[1] + e2 * vf0[2] + e3 * vf0[3]) * inv;
        const float o1 = (e0 * vf1[0] + e1 * vf1[1] + e2 * vf1[2] + e3 * vf1[3]) * inv;
        __nv_bfloat16 hh, ll;
        bsplit(o0, hh, ll);
        g_ath[base + i * 256] = hh;  g_atl[base + i * 256] = ll;
        bsplit(o1, hh, ll);
        g_ath[base + i * 256 + 32] = hh;  g_atl[base + i * 256 + 32] = ll;
    }
}

// ---------------------------------------------------------------------------
// Row epilogues: 1 block (128 threads) per row of 512, 4 elems per thread.
// ---------------------------------------------------------------------------
__device__ __forceinline__ float2 block_sum2_128(float s1, float s2)
{
#pragma unroll
    for (int off = 16; off; off >>= 1) {
        s1 += __shfl_xor_sync(0xffffffffu, s1, off);
        s2 += __shfl_xor_sync(0xffffffffu, s2, off);
    }
    __shared__ float sh[8];
    const int w = threadIdx.x >> 5;
    if ((threadIdx.x & 31) == 0) { sh[w] = s1; sh[w + 4] = s2; }
    __syncthreads();
    return make_float2(sh[0] + sh[1] + sh[2] + sh[3],
                       sh[4] + sh[5] + sh[6] + sh[7]);
}

// z1 = relu(x + roll(LN(zp), +2));  writes z1 fp32 AND z1 hi/lo bf16
__global__ __launch_bounds__(128)
void ln_shift_add_relu(const float* __restrict__ zp, const float* __restrict__ x,
                       const float* __restrict__ g, const float* __restrict__ b,
                       float* __restrict__ z1,
                       __nv_bfloat16* __restrict__ z1h, __nv_bfloat16* __restrict__ z1l)
{
    const size_t row = blockIdx.x;
    const int    c   = threadIdx.x * 4;
    const float4 v   = *(const float4*)(zp + row * 512 + c);
    float2 ss = block_sum2_128(v.x + v.y + v.z + v.w,
                               v.x * v.x + v.y * v.y + v.z * v.z + v.w * v.w);
    const float mu   = ss.x * (1.f / 512.f);
    const float var  = ss.y * (1.f / 512.f) - mu * mu;
    const float rstd = rsqrtf(var + 1e-5f);

    const size_t orow = (row & ~(size_t)255) | ((row + 2) & 255);
    const float4 gg = *(const float4*)(g + c);
    const float4 bb = *(const float4*)(b + c);
    const float4 xv = *(const float4*)(x + orow * 512 + c);
    float4 o;
    o.x = fmaxf(xv.x + (v.x - mu) * rstd * gg.x + bb.x, 0.f);
    o.y = fmaxf(xv.y + (v.y - mu) * rstd * gg.y + bb.y, 0.f);
    o.z = fmaxf(xv.z + (v.z - mu) * rstd * gg.z + bb.z, 0.f);
    o.w = fmaxf(xv.w + (v.w - mu) * rstd * gg.w + bb.w, 0.f);
    *(float4*)(z1 + orow * 512 + c) = o;

    __nv_bfloat16 h0, h1, h2, h3, l0, l1, l2, l3;
    bsplit(o.x, h0, l0); bsplit(o.y, h1, l1);
    bsplit(o.z, h2, l2); bsplit(o.w, h3, l3);
    uint2 uh; uh.x = pack2(h0, h1); uh.y = pack2(h2, h3);
    uint2 ul; ul.x = pack2(l0, l1); ul.y = pack2(l2, l3);
    *(uint2*)(z1h + orow * 512 + c) = uh;
    *(uint2*)(z1l + orow * 512 + c) = ul;
}

// out = relu(z1 + LN(y)); writes ONLY hi/lo bf16 (feeds merge GEMM)
__global__ __launch_bounds__(128)
void ln_add_relu(const float* __restrict__ y, const float* __restrict__ z1,
                 const float* __restrict__ g, const float* __restrict__ b,
                 __nv_bfloat16* __restrict__ oh, __nv_bfloat16* __restrict__ ol)
{
    const size_t row = blockIdx.x;
    const int    c   = threadIdx.x * 4;
    const float4 v   = *(const float4*)(y + row * 512 + c);
    float2 ss = block_sum2_128(v.x + v.y + v.z + v.w,
                               v.x * v.x + v.y * v.y + v.z * v.z + v.w * v.w);
    const float mu   = ss.x * (1.f / 512.f);
    const float var  = ss.y * (1.f / 512.f) - mu * mu;
    const float rstd = rsqrtf(var + 1e-5f);

    const float4 gg = *(const float4*)(g + c);
    const float4 bb = *(const float4*)(b + c);
    const float4 zv = *(const float4*)(z1 + row * 512 + c);
    float4 o;
    o.x = fmaxf(zv.x + (v.x - mu) * rstd * gg.x + bb.x, 0.f);
    o.y = fmaxf(zv.y + (v.y - mu) * rstd * gg.y + bb.y, 0.f);
    o.z = fmaxf(zv.z + (v.z - mu) * rstd * gg.z + bb.z, 0.f);
    o.w = fmaxf(zv.w + (v.w - mu) * rstd * gg.w + bb.w, 0.f);

    __nv_bfloat16 h0, h1, h2, h3, l0, l1, l2, l3;
    bsplit(o.x, h0, l0); bsplit(o.y, h1, l1);
    bsplit(o.z, h2, l2); bsplit(o.w, h3, l3);
    uint2 uh; uh.x = pack2(h0, h1); uh.y = pack2(h2, h3);
    uint2 ul; ul.x = pack2(l0, l1); ul.y = pack2(l2, l3);
    *(uint2*)(oh + row * 512 + c) = uh;
    *(uint2*)(ol + row * 512 + c) = ul;
}

// d_out = relu(LN(y2))
__global__ __launch_bounds__(128)
void ln_relu(const float* __restrict__ y, const float* __restrict__ g,
             const float* __restrict__ b, float* __restrict__ out)
{
    const size_t row = blockIdx.x;
    const int    c   = threadIdx.x * 4;
    const float4 v   = *(const float4*)(y + row * 512 + c);
    float2 ss = block_sum2_128(v.x + v.y + v.z + v.w,
                               v.x * v.x + v.y * v.y + v.z * v.z + v.w * v.w);
    const float mu   = ss.x * (1.f / 512.f);
    const float var  = ss.y * (1.f / 512.f) - mu * mu;
    const float rstd = rsqrtf(var + 1e-5f);

    const float4 gg = *(const float4*)(g + c);
    const float4 bb = *(const float4*)(b + c);
    float4 o;
    o.x = fmaxf((v.x - mu) * rstd * gg.x + bb.x, 0.f);
    o.y = fmaxf((v.y - mu) * rstd * gg.y + bb.y, 0.f);
    o.z = fmaxf((v.z - mu) * rstd * gg.z + bb.z, 0.f);
    o.w = fmaxf((v.w - mu) * rstd * gg.w + bb.w, 0.f);
    *(float4*)(out + row * 512 + c) = o;
}

// ---------------------------------------------------------------------------
extern "C" void kernel_launch(void* const* d_in, const int* in_sizes, int n_in,
                              void* d_out, int out_size)
{
    const float* x     = (const float*)d_in[0];
    const float* Wq    = (const float*)d_in[1];
    const float* bq    = (const float*)d_in[2];
    const float* Wk    = (const float*)d_in[3];
    const float* bk    = (const float*)d_in[4];
    const float* Wv    = (const float*)d_in[5];
    const float* bv    = (const float*)d_in[6];
    const float* aW    = (const float*)d_in[7];
    const float* ab    = (const float*)d_in[8];
    const float* ag    = (const float*)d_in[9];
    const float* abeta = (const float*)d_in[10];
    const float* fW    = (const float*)d_in[11];
    const float* fb    = (const float*)d_in[12];
    const float* fg    = (const float*)d_in[13];
    const float* fbeta = (const float*)d_in[14];
    const float* dW    = (const float*)d_in[15];
    const float* db    = (const float*)d_in[16];
    const float* dg    = (const float*)d_in[17];
    const float* dbeta = (const float*)d_in[18];
    float* out = (float*)d_out;

    float *pq, *pk, *pv, *ptmp, *pz1;
    __nv_bfloat16 *pxh, *pxl, *path, *patl, *pz1h, *pz1l, *poh, *pol, *pwh, *pwl;
    cudaGetSymbolAddress((void**)&pq,   g_q);
    cudaGetSymbolAddress((void**)&pk,   g_k);
    cudaGetSymbolAddress((void**)&pv,   g_v);
    cudaGetSymbolAddress((void**)&ptmp, g_tmp);
    cudaGetSymbolAddress((void**)&pz1,  g_z1);
    cudaGetSymbolAddress((void**)&pxh,  g_xh);
    cudaGetSymbolAddress((void**)&pxl,  g_xl);
    cudaGetSymbolAddress((void**)&path, g_ath);
    cudaGetSymbolAddress((void**)&patl, g_atl);
    cudaGetSymbolAddress((void**)&pz1h, g_z1h);
    cudaGetSymbolAddress((void**)&pz1l, g_z1l);
    cudaGetSymbolAddress((void**)&poh,  g_oh);
    cudaGetSymbolAddress((void**)&pol,  g_ol);
    cudaGetSymbolAddress((void**)&pwh,  g_wh);
    cudaGetSymbolAddress((void**)&pwl,  g_wl);

    cudaFuncSetAttribute(hgemm_bias, cudaFuncAttributeMaxDynamicSharedMemorySize, SMEM_GEMM);
    cudaFuncSetAttribute(hgemm_qkv,  cudaFuncAttributeMaxDynamicSharedMemorySize, SMEM_GEMM);

    // 0) pre-split operands to bf16 hi/lo
    split_x_kernel<<<32768, 256>>>(x, pxh, pxl);
    split_w_kernel<<<5120, 256>>>(Wq, Wk, Wv, aW, fW, dW, pwh, pwl);

    // 1) fused QKV on rolled input: [65536,512] x [512,256]^T (x3 outputs)
    hgemm_qkv<<<dim3(12, 512), 256, SMEM_GEMM>>>(pxh, pxl, pwh, pwl, bq, bk, bv, pq, pk, pv);

    // 2) window attention (emits hi/lo bf16)
    attn_kernel<<<16384, 128>>>();

    // 3) attention projection: [65536,256] x [256,512]^T
    hgemm_bias<<<dim3(8, 512), 256, SMEM_GEMM>>>(path, patl, pwh + OFF_AW, pwl + OFF_AW,
                                                 ab, ptmp, 512, 256);

    // 4) z1 = relu(x + roll(LN(zp), +2))  (+ hi/lo split)
    ln_shift_add_relu<<<65536, 128>>>(ptmp, x, ag, abeta, pz1, pz1h, pz1l);

    // 5) FFN: [65536,512] x [512,512]^T
    hgemm_bias<<<dim3(8, 512), 256, SMEM_GEMM>>>(pz1h, pz1l, pwh + OFF_FW, pwl + OFF_FW,
                                                 fb, ptmp, 512, 512);

    // 6) out = relu(z1 + LN(y))  (hi/lo only; feeds merge GEMM)
    ln_add_relu<<<65536, 128>>>(ptmp, pz1, fg, fbeta, poh, pol);

    // 7/8) patch-merge GEMM: out viewed as [32768,1024] x [1024,512]^T
    hgemm_bias<<<dim3(8, 256), 256, SMEM_GEMM>>>(poh, pol, pwh + OFF_DW, pwl + OFF_DW,
                                                 db, ptmp, 512, 1024);

    // 9) d_out = relu(LN(y2))
    ln_relu<<<32768, 128>>>(ptmp, dg, dbeta, out);
}